// round 2
// baseline (speedup 1.0000x reference)
#include <cuda_runtime.h>
#include <math.h>

#define N_NODES 30000
#define E_EDGES 480000
#define VDIM    512
#define HID     32

// ---- scratch (no allocation allowed; __device__ globals) ----
__device__ float g_h[N_NODES * HID];       // MLP output per node
__device__ float g_agg[N_NODES * HID];     // scatter accumulator
__device__ float g_deg[N_NODES];           // degree accumulator
__device__ float g_rnorm[N_NODES];         // 1 / max(||visual_row||, 1e-8)
__device__ float g_sum[HID];               // BN partial sums
__device__ float g_sumsq[HID];             // BN partial sums of squares
__device__ float g_scale[HID];             // fused BN scale (rstd*gamma)
__device__ float g_shift[HID];             // fused BN shift (beta - mu*scale)
__device__ float g_u[HID];                 // wp @ wc  (fused projection)
__device__ float g_c;                      // wp·bc + bp

// ---------------------------------------------------------------------------
// K0: zero accumulators
// ---------------------------------------------------------------------------
__global__ void k_zero() {
    int i = blockIdx.x * blockDim.x + threadIdx.x;
    int stride = gridDim.x * blockDim.x;
    for (int j = i; j < N_NODES * HID; j += stride) g_agg[j] = 0.f;
    for (int j = i; j < N_NODES; j += stride) g_deg[j] = 0.f;
    if (i < HID) { g_sum[i] = 0.f; g_sumsq[i] = 0.f; }
}

// ---------------------------------------------------------------------------
// K1: BN statistics — h1 = x@w1.T + b1, accumulate per-feature sum / sumsq
// ---------------------------------------------------------------------------
__global__ void k_bnstats(const float* __restrict__ x,
                          const float* __restrict__ w1,
                          const float* __restrict__ b1) {
    int n = blockIdx.x * blockDim.x + threadIdx.x;
    int lane = threadIdx.x & 31;
    bool valid = (n < N_NODES);
    float x0 = 0.f, x1 = 0.f;
    if (valid) { x0 = x[2 * n]; x1 = x[2 * n + 1]; }

#pragma unroll
    for (int k = 0; k < HID; k++) {
        float h = valid ? fmaf(w1[2 * k], x0, fmaf(w1[2 * k + 1], x1, b1[k])) : 0.f;
        float s = h, s2 = h * h;
#pragma unroll
        for (int off = 16; off > 0; off >>= 1) {
            s  += __shfl_xor_sync(0xffffffffu, s,  off);
            s2 += __shfl_xor_sync(0xffffffffu, s2, off);
        }
        if (lane == 0) {
            atomicAdd(&g_sum[k], s);
            atomicAdd(&g_sumsq[k], s2);
        }
    }
}

// ---------------------------------------------------------------------------
// K2: finalize BN affine + fold wc/wp/bc/bp into u, c   (1 block, 32 threads)
// ---------------------------------------------------------------------------
__global__ void k_prep(const float* __restrict__ gamma,
                       const float* __restrict__ beta,
                       const float* __restrict__ wc,
                       const float* __restrict__ bc,
                       const float* __restrict__ wp,
                       const float* __restrict__ bp) {
    int k = threadIdx.x;
    if (k >= HID) return;
    const float invN = 1.0f / (float)N_NODES;
    float mu  = g_sum[k] * invN;
    float var = g_sumsq[k] * invN - mu * mu;
    float rstd = rsqrtf(var + 1e-5f);
    float sc = rstd * gamma[k];
    g_scale[k] = sc;
    g_shift[k] = beta[k] - mu * sc;

    // u[k] = sum_j wp[j] * wc[j][k]
    float u = 0.f;
#pragma unroll
    for (int j = 0; j < HID; j++) u = fmaf(wp[j], wc[j * HID + k], u);
    g_u[k] = u;

    if (k == 0) {
        float c = bp[0];
#pragma unroll
        for (int j = 0; j < HID; j++) c = fmaf(wp[j], bc[j], c);
        g_c = c;
    }
}

// ---------------------------------------------------------------------------
// K3: reciprocal row norms of visual  (one warp per node)
// ---------------------------------------------------------------------------
__global__ void k_rnorm(const float* __restrict__ visual) {
    int gw   = (blockIdx.x * blockDim.x + threadIdx.x) >> 5;
    int lane = threadIdx.x & 31;
    if (gw >= N_NODES) return;
    const float4* v = (const float4*)(visual + (size_t)gw * VDIM);
    float s = 0.f;
#pragma unroll
    for (int i = 0; i < VDIM / 128; i++) {
        float4 f = v[i * 32 + lane];
        s = fmaf(f.x, f.x, s); s = fmaf(f.y, f.y, s);
        s = fmaf(f.z, f.z, s); s = fmaf(f.w, f.w, s);
    }
#pragma unroll
    for (int off = 16; off > 0; off >>= 1) s += __shfl_xor_sync(0xffffffffu, s, off);
    if (lane == 0) g_rnorm[gw] = 1.0f / fmaxf(sqrtf(s), 1e-8f);
}

// ---------------------------------------------------------------------------
// K4: MLP — recompute h1, fused BN, PReLU, 32x32 GEMM -> g_h  (thread/node)
// ---------------------------------------------------------------------------
__global__ void k_mlp(const float* __restrict__ x,
                      const float* __restrict__ w1,
                      const float* __restrict__ b1,
                      const float* __restrict__ prelu_a,
                      const float* __restrict__ w2,
                      const float* __restrict__ b2) {
    __shared__ float sw2[HID * HID];
    __shared__ float sb2[HID];
    __shared__ float ssc[HID], ssh[HID];
    for (int i = threadIdx.x; i < HID * HID; i += blockDim.x) sw2[i] = w2[i];
    if (threadIdx.x < HID) {
        sb2[threadIdx.x] = b2[threadIdx.x];
        ssc[threadIdx.x] = g_scale[threadIdx.x];
        ssh[threadIdx.x] = g_shift[threadIdx.x];
    }
    __syncthreads();

    int n = blockIdx.x * blockDim.x + threadIdx.x;
    if (n >= N_NODES) return;
    float a = prelu_a[0];
    float x0 = x[2 * n], x1 = x[2 * n + 1];

    float hp[HID];
#pragma unroll
    for (int k = 0; k < HID; k++) {
        float h1 = fmaf(w1[2 * k], x0, fmaf(w1[2 * k + 1], x1, b1[k]));
        float h  = fmaf(h1, ssc[k], ssh[k]);
        hp[k] = (h >= 0.f) ? h : a * h;
    }
    float* out = &g_h[(size_t)n * HID];
#pragma unroll
    for (int j = 0; j < HID; j += 4) {
        float4 o;
        float o0 = sb2[j], o1 = sb2[j + 1], o2 = sb2[j + 2], o3 = sb2[j + 3];
#pragma unroll
        for (int k = 0; k < HID; k++) {
            float hk = hp[k];
            o0 = fmaf(hk, sw2[(j + 0) * HID + k], o0);
            o1 = fmaf(hk, sw2[(j + 1) * HID + k], o1);
            o2 = fmaf(hk, sw2[(j + 2) * HID + k], o2);
            o3 = fmaf(hk, sw2[(j + 3) * HID + k], o3);
        }
        o.x = o0; o.y = o1; o.z = o2; o.w = o3;
        *(float4*)(out + j) = o;
    }
}

// ---------------------------------------------------------------------------
// K5: edge kernel — cosine dot (warp/edge) + scatter-add message
// edge_index is int32 on device (JAX default x64-disabled downcasts int64).
// ---------------------------------------------------------------------------
__global__ void k_edge(const float* __restrict__ visual,
                       const int* __restrict__ ei) {
    int gw   = (blockIdx.x * blockDim.x + threadIdx.x) >> 5;
    int lane = threadIdx.x & 31;
    if (gw >= E_EDGES) return;

    int src = ei[gw];
    int dst = ei[E_EDGES + gw];

    const float4* a = (const float4*)(visual + (size_t)src * VDIM);
    const float4* b = (const float4*)(visual + (size_t)dst * VDIM);
    float s = 0.f;
#pragma unroll
    for (int i = 0; i < VDIM / 128; i++) {
        float4 fa = a[i * 32 + lane];
        float4 fb = b[i * 32 + lane];
        s = fmaf(fa.x, fb.x, s); s = fmaf(fa.y, fb.y, s);
        s = fmaf(fa.z, fb.z, s); s = fmaf(fa.w, fb.w, s);
    }
#pragma unroll
    for (int off = 16; off > 0; off >>= 1) s += __shfl_xor_sync(0xffffffffu, s, off);
    // all lanes now hold the full dot
    float w = s * g_rnorm[src] * g_rnorm[dst];

    float msg = w * g_h[(size_t)src * HID + lane];
    atomicAdd(&g_agg[(size_t)dst * HID + lane], msg);
    if (lane == 0) atomicAdd(&g_deg[dst], 1.0f);
}

// ---------------------------------------------------------------------------
// K6: final — scores[n] = dot(agg[n], u)/max(deg,1) + c
// ---------------------------------------------------------------------------
__global__ void k_final(float* __restrict__ out) {
    __shared__ float su[HID];
    if (threadIdx.x < HID) su[threadIdx.x] = g_u[threadIdx.x];
    __syncthreads();
    int n = blockIdx.x * blockDim.x + threadIdx.x;
    if (n >= N_NODES) return;
    const float* ag = &g_agg[(size_t)n * HID];
    float s = 0.f;
#pragma unroll
    for (int k = 0; k < HID; k += 4) {
        float4 a = *(const float4*)(ag + k);
        s = fmaf(a.x, su[k], s);
        s = fmaf(a.y, su[k + 1], s);
        s = fmaf(a.z, su[k + 2], s);
        s = fmaf(a.w, su[k + 3], s);
    }
    out[n] = s / fmaxf(g_deg[n], 1.0f) + g_c;
}

// ---------------------------------------------------------------------------
extern "C" void kernel_launch(void* const* d_in, const int* in_sizes, int n_in,
                              void* d_out, int out_size) {
    const float* x       = (const float*)d_in[0];
    const float* visual  = (const float*)d_in[1];
    const int*   ei      = (const int*)d_in[2];
    const float* w1      = (const float*)d_in[3];
    const float* b1      = (const float*)d_in[4];
    const float* gamma   = (const float*)d_in[5];
    const float* beta    = (const float*)d_in[6];
    const float* prelu_a = (const float*)d_in[7];
    const float* w2      = (const float*)d_in[8];
    const float* b2      = (const float*)d_in[9];
    const float* wc      = (const float*)d_in[10];
    const float* bc      = (const float*)d_in[11];
    const float* wp      = (const float*)d_in[12];
    const float* bp      = (const float*)d_in[13];
    float*       out     = (float*)d_out;

    k_zero<<<1024, 256>>>();
    k_bnstats<<<(N_NODES + 255) / 256, 256>>>(x, w1, b1);
    k_prep<<<1, 32>>>(gamma, beta, wc, bc, wp, bp);
    k_rnorm<<<(N_NODES * 32 + 255) / 256, 256>>>(visual);
    k_mlp<<<(N_NODES + 255) / 256, 256>>>(x, w1, b1, prelu_a, w2, b2);
    k_edge<<<(E_EDGES * 32 + 255) / 256, 256>>>(visual, ei);
    k_final<<<(N_NODES + 255) / 256, 256>>>(out);
}

// round 3
// speedup vs baseline: 1.2643x; 1.2643x over previous
#include <cuda_runtime.h>
#include <cuda_fp16.h>
#include <math.h>

#define N_NODES 30000
#define E_EDGES 480000
#define VDIM    512
#define HID     32

// ---- scratch (__device__ globals; no allocation allowed) ----
__device__ __half g_vh[N_NODES * VDIM];    // normalized visual, fp16 (30.7 MB)
__device__ float  g_p[N_NODES];            // p[n] = h[n] . u   (scalar per node)
__device__ float  g_sacc[N_NODES];         // score accumulator (pre-division)
__device__ float  g_deg[N_NODES];          // degree accumulator
__device__ float  g_sum[HID];              // BN partial sums
__device__ float  g_sumsq[HID];            // BN partial sums of squares
__device__ float  g_scale[HID];            // fused BN scale (rstd*gamma)
__device__ float  g_shift[HID];            // fused BN shift (beta - mu*scale)
__device__ float  g_u[HID];                // wp @ wc  (fused projection)
__device__ float  g_c;                     // wp.bc + bp

// ---------------------------------------------------------------------------
// K0: zero accumulators
// ---------------------------------------------------------------------------
__global__ void k_zero() {
    int i = blockIdx.x * blockDim.x + threadIdx.x;
    int stride = gridDim.x * blockDim.x;
    for (int j = i; j < N_NODES; j += stride) { g_sacc[j] = 0.f; g_deg[j] = 0.f; }
    if (i < HID) { g_sum[i] = 0.f; g_sumsq[i] = 0.f; }
}

// ---------------------------------------------------------------------------
// K1: BN statistics — h1 = x@w1.T + b1, accumulate per-feature sum / sumsq
// ---------------------------------------------------------------------------
__global__ void k_bnstats(const float* __restrict__ x,
                          const float* __restrict__ w1,
                          const float* __restrict__ b1) {
    int n = blockIdx.x * blockDim.x + threadIdx.x;
    int lane = threadIdx.x & 31;
    bool valid = (n < N_NODES);
    float x0 = 0.f, x1 = 0.f;
    if (valid) { x0 = x[2 * n]; x1 = x[2 * n + 1]; }

#pragma unroll
    for (int k = 0; k < HID; k++) {
        float h = valid ? fmaf(w1[2 * k], x0, fmaf(w1[2 * k + 1], x1, b1[k])) : 0.f;
        float s = h, s2 = h * h;
#pragma unroll
        for (int off = 16; off > 0; off >>= 1) {
            s  += __shfl_xor_sync(0xffffffffu, s,  off);
            s2 += __shfl_xor_sync(0xffffffffu, s2, off);
        }
        if (lane == 0) {
            atomicAdd(&g_sum[k], s);
            atomicAdd(&g_sumsq[k], s2);
        }
    }
}

// ---------------------------------------------------------------------------
// K2: finalize BN affine + fold wc/wp/bc/bp into u, c   (1 block, 32 threads)
// ---------------------------------------------------------------------------
__global__ void k_prep(const float* __restrict__ gamma,
                       const float* __restrict__ beta,
                       const float* __restrict__ wc,
                       const float* __restrict__ bc,
                       const float* __restrict__ wp,
                       const float* __restrict__ bp) {
    int k = threadIdx.x;
    if (k >= HID) return;
    const float invN = 1.0f / (float)N_NODES;
    float mu  = g_sum[k] * invN;
    float var = g_sumsq[k] * invN - mu * mu;
    float rstd = rsqrtf(var + 1e-5f);
    float sc = rstd * gamma[k];
    g_scale[k] = sc;
    g_shift[k] = beta[k] - mu * sc;

    // u[k] = sum_j wp[j] * wc[j][k]
    float u = 0.f;
#pragma unroll
    for (int j = 0; j < HID; j++) u = fmaf(wp[j], wc[j * HID + k], u);
    g_u[k] = u;

    if (k == 0) {
        float c = bp[0];
#pragma unroll
        for (int j = 0; j < HID; j++) c = fmaf(wp[j], bc[j], c);
        g_c = c;
    }
}

// ---------------------------------------------------------------------------
// K3: normalize visual rows -> fp16 copy   (one warp per node)
// ---------------------------------------------------------------------------
__global__ void k_vnorm(const float* __restrict__ visual) {
    int gw   = (blockIdx.x * blockDim.x + threadIdx.x) >> 5;
    int lane = threadIdx.x & 31;
    if (gw >= N_NODES) return;
    const float4* v = (const float4*)(visual + (size_t)gw * VDIM);
    float4 f[4];
    float s = 0.f;
#pragma unroll
    for (int i = 0; i < 4; i++) {
        f[i] = v[i * 32 + lane];
        s = fmaf(f[i].x, f[i].x, s); s = fmaf(f[i].y, f[i].y, s);
        s = fmaf(f[i].z, f[i].z, s); s = fmaf(f[i].w, f[i].w, s);
    }
#pragma unroll
    for (int off = 16; off > 0; off >>= 1) s += __shfl_xor_sync(0xffffffffu, s, off);
    float rn = 1.0f / fmaxf(sqrtf(s), 1e-8f);

    // write normalized halves: lane handled floats at j = i*128 + lane*4 + {0..3}
    __half2* out = (__half2*)(g_vh + (size_t)gw * VDIM);
#pragma unroll
    for (int i = 0; i < 4; i++) {
        __half2 h0 = __floats2half2_rn(f[i].x * rn, f[i].y * rn);
        __half2 h1 = __floats2half2_rn(f[i].z * rn, f[i].w * rn);
        // half2 index = (i*128 + lane*4)/2
        uint2 pk;
        pk.x = *(unsigned int*)&h0;
        pk.y = *(unsigned int*)&h1;
        *(uint2*)(out + i * 64 + lane * 2) = pk;
    }
}

// ---------------------------------------------------------------------------
// K4: MLP -> scalar p[n] = (mlp(x)[n]) . u      (thread per node)
// ---------------------------------------------------------------------------
__global__ void k_mlp(const float* __restrict__ x,
                      const float* __restrict__ w1,
                      const float* __restrict__ b1,
                      const float* __restrict__ prelu_a,
                      const float* __restrict__ w2,
                      const float* __restrict__ b2) {
    __shared__ float swu[HID];   // u folded through w2:  wu[k] = sum_j u[j]*w2[j][k]
    __shared__ float ssc[HID], ssh[HID];
    __shared__ float sconst;     // u . b2
    if (threadIdx.x < HID) {
        int k = threadIdx.x;
        float wu = 0.f;
#pragma unroll
        for (int j = 0; j < HID; j++) wu = fmaf(g_u[j], w2[j * HID + k], wu);
        swu[k] = wu;
        ssc[k] = g_scale[k];
        ssh[k] = g_shift[k];
        if (k == 0) {
            float c2 = 0.f;
#pragma unroll
            for (int j = 0; j < HID; j++) c2 = fmaf(g_u[j], b2[j], c2);
            sconst = c2;
        }
    }
    __syncthreads();

    int n = blockIdx.x * blockDim.x + threadIdx.x;
    if (n >= N_NODES) return;
    float a = prelu_a[0];
    float x0 = x[2 * n], x1 = x[2 * n + 1];

    float p = sconst;
#pragma unroll
    for (int k = 0; k < HID; k++) {
        float h1 = fmaf(w1[2 * k], x0, fmaf(w1[2 * k + 1], x1, b1[k]));
        float h  = fmaf(h1, ssc[k], ssh[k]);
        float hp = (h >= 0.f) ? h : a * h;
        p = fmaf(hp, swu[k], p);
    }
    g_p[n] = p;
}

// ---------------------------------------------------------------------------
// K5: edge kernel — fp16 cosine dot (warp/edge) + scalar scatter
// edge_index is int32 on device.
// ---------------------------------------------------------------------------
__global__ void k_edge(const int* __restrict__ ei) {
    int gw   = (blockIdx.x * blockDim.x + threadIdx.x) >> 5;
    int lane = threadIdx.x & 31;
    if (gw >= E_EDGES) return;

    int src = ei[gw];
    int dst = ei[E_EDGES + gw];

    const uint4* a = (const uint4*)(g_vh + (size_t)src * VDIM);
    const uint4* b = (const uint4*)(g_vh + (size_t)dst * VDIM);
    float s = 0.f;
#pragma unroll
    for (int i = 0; i < 2; i++) {
        uint4 ua = a[i * 32 + lane];
        uint4 ub = b[i * 32 + lane];
        float2 fa, fb;
        fa = __half22float2(*(__half2*)&ua.x); fb = __half22float2(*(__half2*)&ub.x);
        s = fmaf(fa.x, fb.x, s); s = fmaf(fa.y, fb.y, s);
        fa = __half22float2(*(__half2*)&ua.y); fb = __half22float2(*(__half2*)&ub.y);
        s = fmaf(fa.x, fb.x, s); s = fmaf(fa.y, fb.y, s);
        fa = __half22float2(*(__half2*)&ua.z); fb = __half22float2(*(__half2*)&ub.z);
        s = fmaf(fa.x, fb.x, s); s = fmaf(fa.y, fb.y, s);
        fa = __half22float2(*(__half2*)&ua.w); fb = __half22float2(*(__half2*)&ub.w);
        s = fmaf(fa.x, fb.x, s); s = fmaf(fa.y, fb.y, s);
    }
#pragma unroll
    for (int off = 16; off > 0; off >>= 1) s += __shfl_xor_sync(0xffffffffu, s, off);

    if (lane == 0) atomicAdd(&g_sacc[dst], s * g_p[src]);
    if (lane == 1) atomicAdd(&g_deg[dst], 1.0f);
}

// ---------------------------------------------------------------------------
// K6: final — scores[n] = sacc[n]/max(deg,1) + c
// ---------------------------------------------------------------------------
__global__ void k_final(float* __restrict__ out) {
    int n = blockIdx.x * blockDim.x + threadIdx.x;
    if (n >= N_NODES) return;
    out[n] = g_sacc[n] / fmaxf(g_deg[n], 1.0f) + g_c;
}

// ---------------------------------------------------------------------------
extern "C" void kernel_launch(void* const* d_in, const int* in_sizes, int n_in,
                              void* d_out, int out_size) {
    const float* x       = (const float*)d_in[0];
    const float* visual  = (const float*)d_in[1];
    const int*   ei      = (const int*)d_in[2];
    const float* w1      = (const float*)d_in[3];
    const float* b1      = (const float*)d_in[4];
    const float* gamma   = (const float*)d_in[5];
    const float* beta    = (const float*)d_in[6];
    const float* prelu_a = (const float*)d_in[7];
    const float* w2      = (const float*)d_in[8];
    const float* b2      = (const float*)d_in[9];
    const float* wc      = (const float*)d_in[10];
    const float* bc      = (const float*)d_in[11];
    const float* wp      = (const float*)d_in[12];
    const float* bp      = (const float*)d_in[13];
    float*       out     = (float*)d_out;

    k_zero<<<256, 256>>>();
    k_bnstats<<<(N_NODES + 255) / 256, 256>>>(x, w1, b1);
    k_prep<<<1, 32>>>(gamma, beta, wc, bc, wp, bp);
    k_vnorm<<<(N_NODES * 32 + 255) / 256, 256>>>(visual);
    k_mlp<<<(N_NODES + 255) / 256, 256>>>(x, w1, b1, prelu_a, w2, b2);
    k_edge<<<(E_EDGES * 32 + 255) / 256, 256>>>(ei);
    k_final<<<(N_NODES + 255) / 256, 256>>>(out);
}

// round 4
// speedup vs baseline: 1.2863x; 1.0175x over previous
#include <cuda_runtime.h>
#include <cuda_fp16.h>
#include <math.h>

#define N_NODES 30000
#define E_EDGES 480000
#define VDIM    512
#define HID     32

// ---- scratch (__device__ globals; no allocation allowed) ----
__device__ __half g_vh[N_NODES * VDIM];   // normalized visual, fp16 (30.7 MB)
__device__ float  g_p[N_NODES];           // p[n] = mlp(x)[n] . u  (scalar per node)
__device__ int    g_cnt[N_NODES];         // in-degree histogram
__device__ int    g_rowstart[N_NODES + 1];// CSR row offsets (by dst)
__device__ int    g_cursor[N_NODES];      // fill cursors
__device__ int    g_csr[E_EDGES];         // src indices grouped by dst
__device__ float  g_sum[HID];             // BN partial sums
__device__ float  g_sumsq[HID];           // BN partial sums of squares
__device__ float  g_scale[HID];           // fused BN scale (rstd*gamma)
__device__ float  g_shift[HID];           // fused BN shift (beta - mu*scale)
__device__ float  g_u[HID];               // wp @ wc  (fused projection)
__device__ float  g_c;                    // wp.bc + bp

// ---------------------------------------------------------------------------
// K0: zero accumulators
// ---------------------------------------------------------------------------
__global__ void k_zero() {
    int i = blockIdx.x * blockDim.x + threadIdx.x;
    int stride = gridDim.x * blockDim.x;
    for (int j = i; j < N_NODES; j += stride) g_cnt[j] = 0;
    if (i < HID) { g_sum[i] = 0.f; g_sumsq[i] = 0.f; }
}

// ---------------------------------------------------------------------------
// K1: BN statistics
// ---------------------------------------------------------------------------
__global__ void k_bnstats(const float* __restrict__ x,
                          const float* __restrict__ w1,
                          const float* __restrict__ b1) {
    int n = blockIdx.x * blockDim.x + threadIdx.x;
    int lane = threadIdx.x & 31;
    bool valid = (n < N_NODES);
    float x0 = 0.f, x1 = 0.f;
    if (valid) { x0 = x[2 * n]; x1 = x[2 * n + 1]; }

#pragma unroll
    for (int k = 0; k < HID; k++) {
        float h = valid ? fmaf(w1[2 * k], x0, fmaf(w1[2 * k + 1], x1, b1[k])) : 0.f;
        float s = h, s2 = h * h;
#pragma unroll
        for (int off = 16; off > 0; off >>= 1) {
            s  += __shfl_xor_sync(0xffffffffu, s,  off);
            s2 += __shfl_xor_sync(0xffffffffu, s2, off);
        }
        if (lane == 0) {
            atomicAdd(&g_sum[k], s);
            atomicAdd(&g_sumsq[k], s2);
        }
    }
}

// ---------------------------------------------------------------------------
// K2: finalize BN affine + fold wc/wp/bc/bp into u, c
// ---------------------------------------------------------------------------
__global__ void k_prep(const float* __restrict__ gamma,
                       const float* __restrict__ beta,
                       const float* __restrict__ wc,
                       const float* __restrict__ bc,
                       const float* __restrict__ wp,
                       const float* __restrict__ bp) {
    int k = threadIdx.x;
    if (k >= HID) return;
    const float invN = 1.0f / (float)N_NODES;
    float mu  = g_sum[k] * invN;
    float var = g_sumsq[k] * invN - mu * mu;
    float rstd = rsqrtf(var + 1e-5f);
    float sc = rstd * gamma[k];
    g_scale[k] = sc;
    g_shift[k] = beta[k] - mu * sc;

    float u = 0.f;
#pragma unroll
    for (int j = 0; j < HID; j++) u = fmaf(wp[j], wc[j * HID + k], u);
    g_u[k] = u;

    if (k == 0) {
        float c = bp[0];
#pragma unroll
        for (int j = 0; j < HID; j++) c = fmaf(wp[j], bc[j], c);
        g_c = c;
    }
}

// ---------------------------------------------------------------------------
// K3: normalize visual rows -> fp16 copy   (one warp per node)
// ---------------------------------------------------------------------------
__global__ void k_vnorm(const float* __restrict__ visual) {
    int gw   = (blockIdx.x * blockDim.x + threadIdx.x) >> 5;
    int lane = threadIdx.x & 31;
    if (gw >= N_NODES) return;
    const float4* v = (const float4*)(visual + (size_t)gw * VDIM);
    float4 f[4];
    float s = 0.f;
#pragma unroll
    for (int i = 0; i < 4; i++) {
        f[i] = v[i * 32 + lane];
        s = fmaf(f[i].x, f[i].x, s); s = fmaf(f[i].y, f[i].y, s);
        s = fmaf(f[i].z, f[i].z, s); s = fmaf(f[i].w, f[i].w, s);
    }
#pragma unroll
    for (int off = 16; off > 0; off >>= 1) s += __shfl_xor_sync(0xffffffffu, s, off);
    float rn = 1.0f / fmaxf(sqrtf(s), 1e-8f);

    __half2* out = (__half2*)(g_vh + (size_t)gw * VDIM);
#pragma unroll
    for (int i = 0; i < 4; i++) {
        __half2 h0 = __floats2half2_rn(f[i].x * rn, f[i].y * rn);
        __half2 h1 = __floats2half2_rn(f[i].z * rn, f[i].w * rn);
        uint2 pk;
        pk.x = *(unsigned int*)&h0;
        pk.y = *(unsigned int*)&h1;
        *(uint2*)(out + i * 64 + lane * 2) = pk;
    }
}

// ---------------------------------------------------------------------------
// K4: MLP -> scalar p[n]   (thread per node)
// ---------------------------------------------------------------------------
__global__ void k_mlp(const float* __restrict__ x,
                      const float* __restrict__ w1,
                      const float* __restrict__ b1,
                      const float* __restrict__ prelu_a,
                      const float* __restrict__ w2,
                      const float* __restrict__ b2) {
    __shared__ float swu[HID];
    __shared__ float ssc[HID], ssh[HID];
    __shared__ float sconst;
    if (threadIdx.x < HID) {
        int k = threadIdx.x;
        float wu = 0.f;
#pragma unroll
        for (int j = 0; j < HID; j++) wu = fmaf(g_u[j], w2[j * HID + k], wu);
        swu[k] = wu;
        ssc[k] = g_scale[k];
        ssh[k] = g_shift[k];
        if (k == 0) {
            float c2 = 0.f;
#pragma unroll
            for (int j = 0; j < HID; j++) c2 = fmaf(g_u[j], b2[j], c2);
            sconst = c2;
        }
    }
    __syncthreads();

    int n = blockIdx.x * blockDim.x + threadIdx.x;
    if (n >= N_NODES) return;
    float a = prelu_a[0];
    float x0 = x[2 * n], x1 = x[2 * n + 1];

    float p = sconst;
#pragma unroll
    for (int k = 0; k < HID; k++) {
        float h1 = fmaf(w1[2 * k], x0, fmaf(w1[2 * k + 1], x1, b1[k]));
        float h  = fmaf(h1, ssc[k], ssh[k]);
        float hp = (h >= 0.f) ? h : a * h;
        p = fmaf(hp, swu[k], p);
    }
    g_p[n] = p;
}

// ---------------------------------------------------------------------------
// K5a: in-degree histogram
// ---------------------------------------------------------------------------
__global__ void k_hist(const int* __restrict__ ei) {
    int i = blockIdx.x * blockDim.x + threadIdx.x;
    int stride = gridDim.x * blockDim.x;
    for (int e = i; e < E_EDGES; e += stride)
        atomicAdd(&g_cnt[ei[E_EDGES + e]], 1);
}

// ---------------------------------------------------------------------------
// K5b: exclusive prefix sum over g_cnt (single block, 1024 threads, looped)
// ---------------------------------------------------------------------------
__global__ void k_scan() {
    __shared__ int warp_sums[32];
    __shared__ int s_carry;
    int tid = threadIdx.x, lane = tid & 31, wid = tid >> 5;
    if (tid == 0) s_carry = 0;
    __syncthreads();

    for (int base = 0; base < N_NODES; base += 1024) {
        int i = base + tid;
        int v = (i < N_NODES) ? g_cnt[i] : 0;
        int xv = v;
#pragma unroll
        for (int off = 1; off < 32; off <<= 1) {
            int y = __shfl_up_sync(0xffffffffu, xv, off);
            if (lane >= off) xv += y;
        }
        if (lane == 31) warp_sums[wid] = xv;
        __syncthreads();
        if (wid == 0) {
            int w = warp_sums[lane];
#pragma unroll
            for (int off = 1; off < 32; off <<= 1) {
                int y = __shfl_up_sync(0xffffffffu, w, off);
                if (lane >= off) w += y;
            }
            warp_sums[lane] = w;
        }
        __syncthreads();
        int prefix = (wid > 0) ? warp_sums[wid - 1] : 0;
        int incl = xv + prefix + s_carry;
        int excl = incl - v;
        if (i < N_NODES) { g_rowstart[i] = excl; g_cursor[i] = excl; }
        __syncthreads();                 // all s_carry reads done
        if (tid == 1023) s_carry = incl; // running total
        __syncthreads();
    }
    if (tid == 0) g_rowstart[N_NODES] = s_carry;
}

// ---------------------------------------------------------------------------
// K5c: CSR fill — group src indices by dst
// ---------------------------------------------------------------------------
__global__ void k_fill(const int* __restrict__ ei) {
    int i = blockIdx.x * blockDim.x + threadIdx.x;
    int stride = gridDim.x * blockDim.x;
    for (int e = i; e < E_EDGES; e += stride) {
        int dst = ei[E_EDGES + e];
        int pos = atomicAdd(&g_cursor[dst], 1);
        g_csr[pos] = ei[e];
    }
}

// ---------------------------------------------------------------------------
// K6: aggregation — warp per dst node.
//   acc (512-dim fp32, 16/lane) = sum over incoming edges of p_src * vn_src;
//   score = (acc . vn_dst) / max(deg,1) + c
// ---------------------------------------------------------------------------
__global__ void k_agg(float* __restrict__ out) {
    int gw   = (blockIdx.x * blockDim.x + threadIdx.x) >> 5;
    int lane = threadIdx.x & 31;
    if (gw >= N_NODES) return;

    int beg = g_rowstart[gw];
    int end = g_rowstart[gw + 1];

    float acc[16];
#pragma unroll
    for (int j = 0; j < 16; j++) acc[j] = 0.f;

    int src_next = (beg < end) ? g_csr[beg] : 0;
    for (int i = beg; i < end; i++) {
        int src = src_next;
        if (i + 1 < end) src_next = g_csr[i + 1];
        float ps = g_p[src];
        const uint4* a = (const uint4*)(g_vh + (size_t)src * VDIM);
        uint4 u0 = a[lane];
        uint4 u1 = a[32 + lane];
        float2 f;
        f = __half22float2(*(__half2*)&u0.x); acc[0]  = fmaf(f.x, ps, acc[0]);  acc[1]  = fmaf(f.y, ps, acc[1]);
        f = __half22float2(*(__half2*)&u0.y); acc[2]  = fmaf(f.x, ps, acc[2]);  acc[3]  = fmaf(f.y, ps, acc[3]);
        f = __half22float2(*(__half2*)&u0.z); acc[4]  = fmaf(f.x, ps, acc[4]);  acc[5]  = fmaf(f.y, ps, acc[5]);
        f = __half22float2(*(__half2*)&u0.w); acc[6]  = fmaf(f.x, ps, acc[6]);  acc[7]  = fmaf(f.y, ps, acc[7]);
        f = __half22float2(*(__half2*)&u1.x); acc[8]  = fmaf(f.x, ps, acc[8]);  acc[9]  = fmaf(f.y, ps, acc[9]);
        f = __half22float2(*(__half2*)&u1.y); acc[10] = fmaf(f.x, ps, acc[10]); acc[11] = fmaf(f.y, ps, acc[11]);
        f = __half22float2(*(__half2*)&u1.z); acc[12] = fmaf(f.x, ps, acc[12]); acc[13] = fmaf(f.y, ps, acc[13]);
        f = __half22float2(*(__half2*)&u1.w); acc[14] = fmaf(f.x, ps, acc[14]); acc[15] = fmaf(f.y, ps, acc[15]);
    }

    // dot with vn_dst
    const uint4* b = (const uint4*)(g_vh + (size_t)gw * VDIM);
    uint4 d0 = b[lane];
    uint4 d1 = b[32 + lane];
    float s = 0.f;
    float2 f;
    f = __half22float2(*(__half2*)&d0.x); s = fmaf(acc[0],  f.x, s); s = fmaf(acc[1],  f.y, s);
    f = __half22float2(*(__half2*)&d0.y); s = fmaf(acc[2],  f.x, s); s = fmaf(acc[3],  f.y, s);
    f = __half22float2(*(__half2*)&d0.z); s = fmaf(acc[4],  f.x, s); s = fmaf(acc[5],  f.y, s);
    f = __half22float2(*(__half2*)&d0.w); s = fmaf(acc[6],  f.x, s); s = fmaf(acc[7],  f.y, s);
    f = __half22float2(*(__half2*)&d1.x); s = fmaf(acc[8],  f.x, s); s = fmaf(acc[9],  f.y, s);
    f = __half22float2(*(__half2*)&d1.y); s = fmaf(acc[10], f.x, s); s = fmaf(acc[11], f.y, s);
    f = __half22float2(*(__half2*)&d1.z); s = fmaf(acc[12], f.x, s); s = fmaf(acc[13], f.y, s);
    f = __half22float2(*(__half2*)&d1.w); s = fmaf(acc[14], f.x, s); s = fmaf(acc[15], f.y, s);

#pragma unroll
    for (int off = 16; off > 0; off >>= 1) s += __shfl_xor_sync(0xffffffffu, s, off);

    if (lane == 0) {
        float deg = (float)(end - beg);
        out[gw] = s / fmaxf(deg, 1.0f) + g_c;
    }
}

// ---------------------------------------------------------------------------
extern "C" void kernel_launch(void* const* d_in, const int* in_sizes, int n_in,
                              void* d_out, int out_size) {
    const float* x       = (const float*)d_in[0];
    const float* visual  = (const float*)d_in[1];
    const int*   ei      = (const int*)d_in[2];
    const float* w1      = (const float*)d_in[3];
    const float* b1      = (const float*)d_in[4];
    const float* gamma   = (const float*)d_in[5];
    const float* beta    = (const float*)d_in[6];
    const float* prelu_a = (const float*)d_in[7];
    const float* w2      = (const float*)d_in[8];
    const float* b2      = (const float*)d_in[9];
    const float* wc      = (const float*)d_in[10];
    const float* bc      = (const float*)d_in[11];
    const float* wp      = (const float*)d_in[12];
    const float* bp      = (const float*)d_in[13];
    float*       out     = (float*)d_out;

    k_zero<<<128, 256>>>();
    k_bnstats<<<(N_NODES + 255) / 256, 256>>>(x, w1, b1);
    k_prep<<<1, 32>>>(gamma, beta, wc, bc, wp, bp);
    k_vnorm<<<(N_NODES * 32 + 255) / 256, 256>>>(visual);
    k_mlp<<<(N_NODES + 255) / 256, 256>>>(x, w1, b1, prelu_a, w2, b2);
    k_hist<<<512, 256>>>(ei);
    k_scan<<<1, 1024>>>();
    k_fill<<<512, 256>>>(ei);
    k_agg<<<(N_NODES * 32 + 255) / 256, 256>>>(out);
}

// round 5
// speedup vs baseline: 1.3842x; 1.0761x over previous
#include <cuda_runtime.h>
#include <cuda_fp16.h>
#include <math.h>

#define N_NODES 30000
#define E_EDGES 480000
#define VDIM    512
#define HID     32

#define SCAN_BLK 512
#define NBLKS ((N_NODES + SCAN_BLK - 1) / SCAN_BLK)   // 59

// ---- scratch (__device__ globals; no allocation allowed) ----
__device__ __half g_vh[N_NODES * VDIM];    // normalized visual, fp16 (30.7 MB)
__device__ float  g_p[N_NODES];            // p[n] = mlp(x)[n] . u
__device__ int    g_cnt[N_NODES];          // in-degree histogram
__device__ int    g_rowstart[N_NODES + 1]; // CSR row offsets (by dst)
__device__ int    g_cursor[N_NODES];       // fill cursors
__device__ int    g_csr[E_EDGES];          // src indices grouped by dst
__device__ int    g_bsum[NBLKS];           // scan block sums
__device__ int    g_boff[NBLKS];           // scan block offsets
__device__ float  g_sum[HID];
__device__ float  g_sumsq[HID];
__device__ float  g_scale[HID];
__device__ float  g_shift[HID];
__device__ float  g_u[HID];
__device__ float  g_c;

// ---------------------------------------------------------------------------
__global__ void k_zero() {
    int i = blockIdx.x * blockDim.x + threadIdx.x;
    int stride = gridDim.x * blockDim.x;
    for (int j = i; j < N_NODES; j += stride) g_cnt[j] = 0;
    if (i < HID) { g_sum[i] = 0.f; g_sumsq[i] = 0.f; }
}

// ---------------------------------------------------------------------------
__global__ void k_bnstats(const float* __restrict__ x,
                          const float* __restrict__ w1,
                          const float* __restrict__ b1) {
    int n = blockIdx.x * blockDim.x + threadIdx.x;
    int lane = threadIdx.x & 31;
    bool valid = (n < N_NODES);
    float x0 = 0.f, x1 = 0.f;
    if (valid) { x0 = x[2 * n]; x1 = x[2 * n + 1]; }

#pragma unroll
    for (int k = 0; k < HID; k++) {
        float h = valid ? fmaf(w1[2 * k], x0, fmaf(w1[2 * k + 1], x1, b1[k])) : 0.f;
        float s = h, s2 = h * h;
#pragma unroll
        for (int off = 16; off > 0; off >>= 1) {
            s  += __shfl_xor_sync(0xffffffffu, s,  off);
            s2 += __shfl_xor_sync(0xffffffffu, s2, off);
        }
        if (lane == 0) {
            atomicAdd(&g_sum[k], s);
            atomicAdd(&g_sumsq[k], s2);
        }
    }
}

// ---------------------------------------------------------------------------
__global__ void k_prep(const float* __restrict__ gamma,
                       const float* __restrict__ beta,
                       const float* __restrict__ wc,
                       const float* __restrict__ bc,
                       const float* __restrict__ wp,
                       const float* __restrict__ bp) {
    int k = threadIdx.x;
    if (k >= HID) return;
    const float invN = 1.0f / (float)N_NODES;
    float mu  = g_sum[k] * invN;
    float var = g_sumsq[k] * invN - mu * mu;
    float rstd = rsqrtf(var + 1e-5f);
    float sc = rstd * gamma[k];
    g_scale[k] = sc;
    g_shift[k] = beta[k] - mu * sc;

    float u = 0.f;
#pragma unroll
    for (int j = 0; j < HID; j++) u = fmaf(wp[j], wc[j * HID + k], u);
    g_u[k] = u;

    if (k == 0) {
        float c = bp[0];
#pragma unroll
        for (int j = 0; j < HID; j++) c = fmaf(wp[j], bc[j], c);
        g_c = c;
    }
}

// ---------------------------------------------------------------------------
__global__ void k_vnorm(const float* __restrict__ visual) {
    int gw   = (blockIdx.x * blockDim.x + threadIdx.x) >> 5;
    int lane = threadIdx.x & 31;
    if (gw >= N_NODES) return;
    const float4* v = (const float4*)(visual + (size_t)gw * VDIM);
    float4 f[4];
    float s = 0.f;
#pragma unroll
    for (int i = 0; i < 4; i++) {
        f[i] = v[i * 32 + lane];
        s = fmaf(f[i].x, f[i].x, s); s = fmaf(f[i].y, f[i].y, s);
        s = fmaf(f[i].z, f[i].z, s); s = fmaf(f[i].w, f[i].w, s);
    }
#pragma unroll
    for (int off = 16; off > 0; off >>= 1) s += __shfl_xor_sync(0xffffffffu, s, off);
    float rn = 1.0f / fmaxf(sqrtf(s), 1e-8f);

    __half2* out = (__half2*)(g_vh + (size_t)gw * VDIM);
#pragma unroll
    for (int i = 0; i < 4; i++) {
        __half2 h0 = __floats2half2_rn(f[i].x * rn, f[i].y * rn);
        __half2 h1 = __floats2half2_rn(f[i].z * rn, f[i].w * rn);
        uint2 pk;
        pk.x = *(unsigned int*)&h0;
        pk.y = *(unsigned int*)&h1;
        *(uint2*)(out + i * 64 + lane * 2) = pk;
    }
}

// ---------------------------------------------------------------------------
__global__ void k_mlp(const float* __restrict__ x,
                      const float* __restrict__ w1,
                      const float* __restrict__ b1,
                      const float* __restrict__ prelu_a,
                      const float* __restrict__ w2,
                      const float* __restrict__ b2) {
    __shared__ float swu[HID];
    __shared__ float ssc[HID], ssh[HID];
    __shared__ float sconst;
    if (threadIdx.x < HID) {
        int k = threadIdx.x;
        float wu = 0.f;
#pragma unroll
        for (int j = 0; j < HID; j++) wu = fmaf(g_u[j], w2[j * HID + k], wu);
        swu[k] = wu;
        ssc[k] = g_scale[k];
        ssh[k] = g_shift[k];
        if (k == 0) {
            float c2 = 0.f;
#pragma unroll
            for (int j = 0; j < HID; j++) c2 = fmaf(g_u[j], b2[j], c2);
            sconst = c2;
        }
    }
    __syncthreads();

    int n = blockIdx.x * blockDim.x + threadIdx.x;
    if (n >= N_NODES) return;
    float a = prelu_a[0];
    float x0 = x[2 * n], x1 = x[2 * n + 1];

    float p = sconst;
#pragma unroll
    for (int k = 0; k < HID; k++) {
        float h1 = fmaf(w1[2 * k], x0, fmaf(w1[2 * k + 1], x1, b1[k]));
        float h  = fmaf(h1, ssc[k], ssh[k]);
        float hp = (h >= 0.f) ? h : a * h;
        p = fmaf(hp, swu[k], p);
    }
    g_p[n] = p;
}

// ---------------------------------------------------------------------------
__global__ void k_hist(const int* __restrict__ ei) {
    int i = blockIdx.x * blockDim.x + threadIdx.x;
    int stride = gridDim.x * blockDim.x;
    for (int e = i; e < E_EDGES; e += stride)
        atomicAdd(&g_cnt[ei[E_EDGES + e]], 1);
}

// ---------------------------------------------------------------------------
// Scan phase 1: per-block exclusive scan; block totals -> g_bsum
// ---------------------------------------------------------------------------
__global__ void k_scan1() {
    __shared__ int wsum[SCAN_BLK / 32];
    int b = blockIdx.x, tid = threadIdx.x, lane = tid & 31, wid = tid >> 5;
    int i = b * SCAN_BLK + tid;
    int v = (i < N_NODES) ? g_cnt[i] : 0;
    int xv = v;
#pragma unroll
    for (int off = 1; off < 32; off <<= 1) {
        int y = __shfl_up_sync(0xffffffffu, xv, off);
        if (lane >= off) xv += y;
    }
    if (lane == 31) wsum[wid] = xv;
    __syncthreads();
    if (tid == 0) {
        int run = 0;
#pragma unroll
        for (int k = 0; k < SCAN_BLK / 32; k++) { int t = wsum[k]; wsum[k] = run; run += t; }
        g_bsum[b] = run;
    }
    __syncthreads();
    if (i < N_NODES) g_rowstart[i] = xv - v + wsum[wid];  // block-local exclusive
}

// ---------------------------------------------------------------------------
// Scan phase 2: 1 warp scans the 59 block sums -> exclusive g_boff
// ---------------------------------------------------------------------------
__global__ void k_scan2() {
    int lane = threadIdx.x;
    int v0 = (lane < NBLKS) ? g_bsum[lane] : 0;
    int v1 = (lane + 32 < NBLKS) ? g_bsum[lane + 32] : 0;
    int x0 = v0, x1 = v1;
#pragma unroll
    for (int off = 1; off < 32; off <<= 1) {
        int y = __shfl_up_sync(0xffffffffu, x0, off);
        if (lane >= off) x0 += y;
        int z = __shfl_up_sync(0xffffffffu, x1, off);
        if (lane >= off) x1 += z;
    }
    int tot0 = __shfl_sync(0xffffffffu, x0, 31);
    x1 += tot0;
    if (lane < NBLKS) g_boff[lane] = x0 - v0;
    if (lane + 32 < NBLKS) g_boff[lane + 32] = x1 - v1;
    if (lane == 0) g_rowstart[N_NODES] = E_EDGES;
}

// ---------------------------------------------------------------------------
// Scan phase 3: add block offsets, init cursors
// ---------------------------------------------------------------------------
__global__ void k_scan3() {
    int i = blockIdx.x * blockDim.x + threadIdx.x;
    if (i >= N_NODES) return;
    int r = g_rowstart[i] + g_boff[i / SCAN_BLK];
    g_rowstart[i] = r;
    g_cursor[i] = r;
}

// ---------------------------------------------------------------------------
__global__ void k_fill(const int* __restrict__ ei) {
    int i = blockIdx.x * blockDim.x + threadIdx.x;
    int stride = gridDim.x * blockDim.x;
    for (int e = i; e < E_EDGES; e += stride) {
        int dst = ei[E_EDGES + e];
        int pos = atomicAdd(&g_cursor[dst], 1);
        g_csr[pos] = ei[e];
    }
}

// ---------------------------------------------------------------------------
// K6: aggregation — warp per dst node, edge metadata gathered 32-wide,
// row loads software-pipelined 2 deep.
// ---------------------------------------------------------------------------
__global__ void k_agg(float* __restrict__ out) {
    int gw   = (blockIdx.x * blockDim.x + threadIdx.x) >> 5;
    int lane = threadIdx.x & 31;
    if (gw >= N_NODES) return;

    int beg = g_rowstart[gw];
    int end = g_rowstart[gw + 1];

    float acc[16];
#pragma unroll
    for (int j = 0; j < 16; j++) acc[j] = 0.f;

    for (int base = beg; base < end; base += 32) {
        int cnt = min(32, end - base);
        // gather all edge metadata in parallel (one lane per edge)
        int   src = 0;
        float ps  = 0.f;
        if (lane < cnt) {
            src = __ldg(&g_csr[base + lane]);
            ps  = __ldg(&g_p[src]);
        }
        // pipelined row loop
        int   s0 = __shfl_sync(0xffffffffu, src, 0);
        float p0 = __shfl_sync(0xffffffffu, ps, 0);
        const uint4* r0 = (const uint4*)(g_vh + (size_t)s0 * VDIM);
        uint4 a0 = r0[lane];
        uint4 a1 = r0[32 + lane];

        for (int j = 0; j < cnt; j++) {
            uint4 b0, b1;
            float p1 = 0.f;
            if (j + 1 < cnt) {
                int s1 = __shfl_sync(0xffffffffu, src, j + 1);
                p1 = __shfl_sync(0xffffffffu, ps, j + 1);
                const uint4* rn = (const uint4*)(g_vh + (size_t)s1 * VDIM);
                b0 = rn[lane];
                b1 = rn[32 + lane];
            } else {
                b0 = a0; b1 = a1;
            }
            float2 f;
            f = __half22float2(*(__half2*)&a0.x); acc[0]  = fmaf(f.x, p0, acc[0]);  acc[1]  = fmaf(f.y, p0, acc[1]);
            f = __half22float2(*(__half2*)&a0.y); acc[2]  = fmaf(f.x, p0, acc[2]);  acc[3]  = fmaf(f.y, p0, acc[3]);
            f = __half22float2(*(__half2*)&a0.z); acc[4]  = fmaf(f.x, p0, acc[4]);  acc[5]  = fmaf(f.y, p0, acc[5]);
            f = __half22float2(*(__half2*)&a0.w); acc[6]  = fmaf(f.x, p0, acc[6]);  acc[7]  = fmaf(f.y, p0, acc[7]);
            f = __half22float2(*(__half2*)&a1.x); acc[8]  = fmaf(f.x, p0, acc[8]);  acc[9]  = fmaf(f.y, p0, acc[9]);
            f = __half22float2(*(__half2*)&a1.y); acc[10] = fmaf(f.x, p0, acc[10]); acc[11] = fmaf(f.y, p0, acc[11]);
            f = __half22float2(*(__half2*)&a1.z); acc[12] = fmaf(f.x, p0, acc[12]); acc[13] = fmaf(f.y, p0, acc[13]);
            f = __half22float2(*(__half2*)&a1.w); acc[14] = fmaf(f.x, p0, acc[14]); acc[15] = fmaf(f.y, p0, acc[15]);
            a0 = b0; a1 = b1; p0 = p1;
        }
    }

    // dot with vn_dst
    const uint4* b = (const uint4*)(g_vh + (size_t)gw * VDIM);
    uint4 d0 = b[lane];
    uint4 d1 = b[32 + lane];
    float s = 0.f;
    float2 f;
    f = __half22float2(*(__half2*)&d0.x); s = fmaf(acc[0],  f.x, s); s = fmaf(acc[1],  f.y, s);
    f = __half22float2(*(__half2*)&d0.y); s = fmaf(acc[2],  f.x, s); s = fmaf(acc[3],  f.y, s);
    f = __half22float2(*(__half2*)&d0.z); s = fmaf(acc[4],  f.x, s); s = fmaf(acc[5],  f.y, s);
    f = __half22float2(*(__half2*)&d0.w); s = fmaf(acc[6],  f.x, s); s = fmaf(acc[7],  f.y, s);
    f = __half22float2(*(__half2*)&d1.x); s = fmaf(acc[8],  f.x, s); s = fmaf(acc[9],  f.y, s);
    f = __half22float2(*(__half2*)&d1.y); s = fmaf(acc[10], f.x, s); s = fmaf(acc[11], f.y, s);
    f = __half22float2(*(__half2*)&d1.z); s = fmaf(acc[12], f.x, s); s = fmaf(acc[13], f.y, s);
    f = __half22float2(*(__half2*)&d1.w); s = fmaf(acc[14], f.x, s); s = fmaf(acc[15], f.y, s);

#pragma unroll
    for (int off = 16; off > 0; off >>= 1) s += __shfl_xor_sync(0xffffffffu, s, off);

    if (lane == 0) {
        float deg = (float)(end - beg);
        out[gw] = s / fmaxf(deg, 1.0f) + g_c;
    }
}

// ---------------------------------------------------------------------------
extern "C" void kernel_launch(void* const* d_in, const int* in_sizes, int n_in,
                              void* d_out, int out_size) {
    const float* x       = (const float*)d_in[0];
    const float* visual  = (const float*)d_in[1];
    const int*   ei      = (const int*)d_in[2];
    const float* w1      = (const float*)d_in[3];
    const float* b1      = (const float*)d_in[4];
    const float* gamma   = (const float*)d_in[5];
    const float* beta    = (const float*)d_in[6];
    const float* prelu_a = (const float*)d_in[7];
    const float* w2      = (const float*)d_in[8];
    const float* b2      = (const float*)d_in[9];
    const float* wc      = (const float*)d_in[10];
    const float* bc      = (const float*)d_in[11];
    const float* wp      = (const float*)d_in[12];
    const float* bp      = (const float*)d_in[13];
    float*       out     = (float*)d_out;

    k_zero<<<128, 256>>>();
    k_bnstats<<<(N_NODES + 255) / 256, 256>>>(x, w1, b1);
    k_prep<<<1, 32>>>(gamma, beta, wc, bc, wp, bp);
    k_vnorm<<<(N_NODES * 32 + 255) / 256, 256>>>(visual);
    k_mlp<<<(N_NODES + 255) / 256, 256>>>(x, w1, b1, prelu_a, w2, b2);
    k_hist<<<512, 256>>>(ei);
    k_scan1<<<NBLKS, SCAN_BLK>>>();
    k_scan2<<<1, 32>>>();
    k_scan3<<<(N_NODES + 255) / 256, 256>>>();
    k_fill<<<512, 256>>>(ei);
    k_agg<<<(N_NODES * 32 + 255) / 256, 256>>>(out);
}